// round 13
// baseline (speedup 1.0000x reference)
#include <cuda_runtime.h>
#include <cstddef>

// PCEN transform:
//   m_t = (1-S)*m_{t-1} + S*x_t   (EMA over time axis, per [b,f] row)
//   out = (x / (m+EPS)^ALPHA + DELTA)^R - DELTA^R,  R = 0.5
//
// R12: each warp owns TWO rows, processing one 256-elem chunk of each per
// iteration. The two affine warp scans are independent -> ILP 2 on the
// SHFL dependency chain (the R11 bottleneck). 8 elems/lane per row.
// Exclusive prefix arithmetically: excl = (v - b) * c^-8 (no extra SHFL).
// Recurrence on q-scale (q_t = c*q_{t-1} + x_t, m = S*q).

#define S_CONST     0.025f
#define C_CONST     0.975f
#define EPS_CONST   1e-6f
#define ALPHA_CONST 0.98f
#define DELTA_CONST 2.0f
#define SQRT_DELTA  1.41421356237309515f   // sqrt(2)

#define T_LEN   4096
#define CHUNK   256               // elements per warp-chunk per row (32 x 8)
#define NCHUNK  (T_LEN / CHUNK)   // 16
#define WARPS_PER_BLOCK 4
#define BLOCK_THREADS   (WARPS_PER_BLOCK * 32)

__device__ __forceinline__ float ex2_approx(float a) {
    float r; asm("ex2.approx.f32 %0, %1;" : "=f"(r) : "f"(a)); return r;
}
__device__ __forceinline__ float lg2_approx(float a) {
    float r; asm("lg2.approx.f32 %0, %1;" : "=f"(r) : "f"(a)); return r;
}
__device__ __forceinline__ float sqrt_approx(float a) {
    float r; asm("sqrt.approx.f32 %0, %1;" : "=f"(r) : "f"(a)); return r;
}

// fused epilogue on q-scale: m = S*q
//   (x * (S*q + EPS)^-ALPHA + DELTA)^0.5 - DELTA^0.5
__device__ __forceinline__ float pcen_epilogue(float xv, float q) {
    float p = ex2_approx(-ALPHA_CONST * lg2_approx(fmaf(S_CONST, q, EPS_CONST)));
    return sqrt_approx(fmaf(xv, p, DELTA_CONST)) - SQRT_DELTA;
}

__global__ __launch_bounds__(BLOCK_THREADS, 7)
void pcen_kernel(const float* __restrict__ x, float* __restrict__ out, int nrows)
{
    const int gwarp = (blockIdx.x * BLOCK_THREADS + threadIdx.x) >> 5;
    const int lane  = threadIdx.x & 31;
    const int row0  = gwarp * 2;
    if (row0 >= nrows) return;

    // lane's 8-element segment base within each chunk, for each row
    const float* xr0 = x   + (size_t)row0 * T_LEN + lane * 8;
    const float* xr1 = xr0 + T_LEN;
    float*       ow0 = out + (size_t)row0 * T_LEN + lane * 8;
    float*       ow1 = ow0 + T_LEN;

    // Decay powers (compile-time constants except clane)
    const float c2   = C_CONST * C_CONST;
    const float c4   = c2 * c2;
    const float f1   = c4 * c4;     // c^8   (per-lane segment factor)
    const float f2   = f1 * f1;     // c^16
    const float f3   = f2 * f2;     // c^32
    const float f4   = f3 * f3;     // c^64
    const float f5   = f4 * f4;     // c^128
    const float cchk = f5 * f5;     // c^256 (per-chunk carry factor)
    const float inv_f1 = 1.0f / f1; // c^-8
    // c^(8*lane) via MUFU (once per thread)
    const float clane = ex2_approx(8.0f * (float)lane * lg2_approx(C_CONST));

    float carry0 = 0.0f, carry1 = 0.0f;

    // Prefetch chunk 0 of both rows (4 independent 16B loads in flight)
    float4 a0 = reinterpret_cast<const float4*>(xr0)[0];
    float4 b0 = reinterpret_cast<const float4*>(xr0)[1];
    float4 a1 = reinterpret_cast<const float4*>(xr1)[0];
    float4 b1 = reinterpret_cast<const float4*>(xr1)[1];

    #pragma unroll 1
    for (int ch = 0; ch < NCHUNK; ++ch) {
        // Prefetch next chunk of both rows
        float4 pa0 = a0, pb0 = b0, pa1 = a1, pb1 = b1;
        if (ch + 1 < NCHUNK) {
            const float* n0 = xr0 + (ch + 1) * CHUNK;
            const float* n1 = xr1 + (ch + 1) * CHUNK;
            pa0 = reinterpret_cast<const float4*>(n0)[0];
            pb0 = reinterpret_cast<const float4*>(n0)[1];
            pa1 = reinterpret_cast<const float4*>(n1)[0];
            pb1 = reinterpret_cast<const float4*>(n1)[1];
        }

        // ---- local q-recurrences (independent chains, interleaved) ----
        float s0 = a0.x, s1 = a1.x;
        s0 = fmaf(C_CONST, s0, a0.y);  s1 = fmaf(C_CONST, s1, a1.y);
        s0 = fmaf(C_CONST, s0, a0.z);  s1 = fmaf(C_CONST, s1, a1.z);
        s0 = fmaf(C_CONST, s0, a0.w);  s1 = fmaf(C_CONST, s1, a1.w);
        s0 = fmaf(C_CONST, s0, b0.x);  s1 = fmaf(C_CONST, s1, b1.x);
        s0 = fmaf(C_CONST, s0, b0.y);  s1 = fmaf(C_CONST, s1, b1.y);
        s0 = fmaf(C_CONST, s0, b0.z);  s1 = fmaf(C_CONST, s1, b1.z);
        s0 = fmaf(C_CONST, s0, b0.w);  s1 = fmaf(C_CONST, s1, b1.w);

        // ---- two independent inclusive affine warp scans, interleaved ----
        float v0 = s0, v1 = s1, u0, u1;
        u0 = __shfl_up_sync(0xffffffffu, v0, 1);
        u1 = __shfl_up_sync(0xffffffffu, v1, 1);
        if (lane >= 1)  { v0 = fmaf(f1, u0, v0);  v1 = fmaf(f1, u1, v1); }
        u0 = __shfl_up_sync(0xffffffffu, v0, 2);
        u1 = __shfl_up_sync(0xffffffffu, v1, 2);
        if (lane >= 2)  { v0 = fmaf(f2, u0, v0);  v1 = fmaf(f2, u1, v1); }
        u0 = __shfl_up_sync(0xffffffffu, v0, 4);
        u1 = __shfl_up_sync(0xffffffffu, v1, 4);
        if (lane >= 4)  { v0 = fmaf(f3, u0, v0);  v1 = fmaf(f3, u1, v1); }
        u0 = __shfl_up_sync(0xffffffffu, v0, 8);
        u1 = __shfl_up_sync(0xffffffffu, v1, 8);
        if (lane >= 8)  { v0 = fmaf(f4, u0, v0);  v1 = fmaf(f4, u1, v1); }
        u0 = __shfl_up_sync(0xffffffffu, v0, 16);
        u1 = __shfl_up_sync(0xffffffffu, v1, 16);
        if (lane >= 16) { v0 = fmaf(f5, u0, v0);  v1 = fmaf(f5, u1, v1); }

        // exclusive prefixes, arithmetically (exact 0 at lane 0)
        float e0 = (v0 - s0) * inv_f1;
        float e1 = (v1 - s1) * inv_f1;

        // fold cross-chunk carries
        float q0 = fmaf(clane, carry0, e0);
        float q1 = fmaf(clane, carry1, e1);

        // carries for next chunk (lane 31 broadcasts)
        float w0 = __shfl_sync(0xffffffffu, v0, 31);
        float w1 = __shfl_sync(0xffffffffu, v1, 31);
        carry0 = fmaf(cchk, carry0, w0);
        carry1 = fmaf(cchk, carry1, w1);

        // ---- reconstruct q per element + fused PCEN epilogue (interleaved) ----
        float4 oa0, ob0, oa1, ob1;
        q0 = fmaf(C_CONST, q0, a0.x);  q1 = fmaf(C_CONST, q1, a1.x);
        oa0.x = pcen_epilogue(a0.x, q0);  oa1.x = pcen_epilogue(a1.x, q1);
        q0 = fmaf(C_CONST, q0, a0.y);  q1 = fmaf(C_CONST, q1, a1.y);
        oa0.y = pcen_epilogue(a0.y, q0);  oa1.y = pcen_epilogue(a1.y, q1);
        q0 = fmaf(C_CONST, q0, a0.z);  q1 = fmaf(C_CONST, q1, a1.z);
        oa0.z = pcen_epilogue(a0.z, q0);  oa1.z = pcen_epilogue(a1.z, q1);
        q0 = fmaf(C_CONST, q0, a0.w);  q1 = fmaf(C_CONST, q1, a1.w);
        oa0.w = pcen_epilogue(a0.w, q0);  oa1.w = pcen_epilogue(a1.w, q1);
        q0 = fmaf(C_CONST, q0, b0.x);  q1 = fmaf(C_CONST, q1, b1.x);
        ob0.x = pcen_epilogue(b0.x, q0);  ob1.x = pcen_epilogue(b1.x, q1);
        q0 = fmaf(C_CONST, q0, b0.y);  q1 = fmaf(C_CONST, q1, b1.y);
        ob0.y = pcen_epilogue(b0.y, q0);  ob1.y = pcen_epilogue(b1.y, q1);
        q0 = fmaf(C_CONST, q0, b0.z);  q1 = fmaf(C_CONST, q1, b1.z);
        ob0.z = pcen_epilogue(b0.z, q0);  ob1.z = pcen_epilogue(b1.z, q1);
        q0 = fmaf(C_CONST, q0, b0.w);  q1 = fmaf(C_CONST, q1, b1.w);
        ob0.w = pcen_epilogue(b0.w, q0);  ob1.w = pcen_epilogue(b1.w, q1);

        float* d0 = ow0 + ch * CHUNK;
        float* d1 = ow1 + ch * CHUNK;
        reinterpret_cast<float4*>(d0)[0] = oa0;
        reinterpret_cast<float4*>(d0)[1] = ob0;
        reinterpret_cast<float4*>(d1)[0] = oa1;
        reinterpret_cast<float4*>(d1)[1] = ob1;

        a0 = pa0;  b0 = pb0;  a1 = pa1;  b1 = pb1;
    }
}

extern "C" void kernel_launch(void* const* d_in, const int* in_sizes, int n_in,
                              void* d_out, int out_size)
{
    const float* x = (const float*)d_in[0];
    float* out = (float*)d_out;

    int nrows  = in_sizes[0] / T_LEN;           // 32*256 = 8192
    int nwarps = (nrows + 1) / 2;               // 4096
    int blocks = (nwarps + WARPS_PER_BLOCK - 1) / WARPS_PER_BLOCK;  // 1024

    pcen_kernel<<<blocks, BLOCK_THREADS>>>(x, out, nrows);
}

// round 15
// speedup vs baseline: 1.1018x; 1.1018x over previous
#include <cuda_runtime.h>
#include <cstddef>

// PCEN transform:
//   m_t = (1-S)*m_{t-1} + S*x_t   (EMA over time axis, per [b,f] row)
//   out = (x / (m+EPS)^ALPHA + DELTA)^R - DELTA^R,  R = 0.5
//
// R13: back to the best-bench shape (warp per row, 4 elems/lane, CHUNK=128,
// 8 warps/block) with R10's instruction diet (q-scale recurrence,
// sqrt.approx, arithmetic exclusive prefix) plus a depth-2 prefetch
// pipeline: two LDG.128 in flight per warp at all times.

#define S_CONST     0.025f
#define C_CONST     0.975f
#define EPS_CONST   1e-6f
#define ALPHA_CONST 0.98f
#define DELTA_CONST 2.0f
#define SQRT_DELTA  1.41421356237309515f   // sqrt(2)

#define T_LEN   4096
#define CHUNK   128               // elements per warp-chunk (32 lanes x 4)
#define NCHUNK  (T_LEN / CHUNK)   // 32
#define WARPS_PER_BLOCK 8
#define BLOCK_THREADS   (WARPS_PER_BLOCK * 32)

__device__ __forceinline__ float ex2_approx(float a) {
    float r; asm("ex2.approx.f32 %0, %1;" : "=f"(r) : "f"(a)); return r;
}
__device__ __forceinline__ float lg2_approx(float a) {
    float r; asm("lg2.approx.f32 %0, %1;" : "=f"(r) : "f"(a)); return r;
}
__device__ __forceinline__ float sqrt_approx(float a) {
    float r; asm("sqrt.approx.f32 %0, %1;" : "=f"(r) : "f"(a)); return r;
}

// fused epilogue on q-scale: m = S*q
//   (x * (S*q + EPS)^-ALPHA + DELTA)^0.5 - DELTA^0.5
__device__ __forceinline__ float pcen_epilogue(float xv, float q) {
    float p = ex2_approx(-ALPHA_CONST * lg2_approx(fmaf(S_CONST, q, EPS_CONST)));
    return sqrt_approx(fmaf(xv, p, DELTA_CONST)) - SQRT_DELTA;
}

__global__ __launch_bounds__(BLOCK_THREADS, 6)
void pcen_kernel(const float* __restrict__ x, float* __restrict__ out, int nrows)
{
    const int gwarp = (blockIdx.x * BLOCK_THREADS + threadIdx.x) >> 5;
    const int lane  = threadIdx.x & 31;
    if (gwarp >= nrows) return;

    const float* xr  = x   + (size_t)gwarp * T_LEN + lane * 4;
    float*       orw = out + (size_t)gwarp * T_LEN + lane * 4;

    // Decay powers (compile-time folds for all but clane)
    const float c2   = C_CONST * C_CONST;
    const float f1   = c2 * c2;     // c^4   (per-lane segment factor)
    const float f2   = f1 * f1;     // c^8
    const float f3   = f2 * f2;     // c^16
    const float f4   = f3 * f3;     // c^32
    const float f5   = f4 * f4;     // c^64
    const float cchk = f5 * f5;     // c^128 (per-chunk carry factor)
    const float inv_f1 = 1.0f / f1; // c^-4
    // c^(4*lane) via MUFU (once per thread)
    const float clane = ex2_approx(4.0f * (float)lane * lg2_approx(C_CONST));

    float carry = 0.0f;   // q-scale carry entering this chunk

    // Depth-2 prefetch pipeline: chunks 0 and 1 in flight before the loop.
    float4 cur = reinterpret_cast<const float4*>(xr)[0];
    float4 nxt = reinterpret_cast<const float4*>(xr + CHUNK)[0];

    #pragma unroll 1
    for (int ch = 0; ch < NCHUNK; ++ch) {
        // Issue load for chunk ch+2 (keeps 2 LDG.128 outstanding)
        float4 nxt2 = nxt;
        if (ch + 2 < NCHUNK)
            nxt2 = reinterpret_cast<const float4*>(xr + (ch + 2) * CHUNK)[0];

        // ---- local q-recurrence of this lane's 4 elements (zero-init) ----
        float b = cur.x;
        b = fmaf(C_CONST, b, cur.y);
        b = fmaf(C_CONST, b, cur.z);
        b = fmaf(C_CONST, b, cur.w);

        // ---- inclusive affine warp scan: v_l = b_l + c^4 * v_{l-1} ----
        float v = b, u;
        u = __shfl_up_sync(0xffffffffu, v, 1);  if (lane >= 1)  v = fmaf(f1, u, v);
        u = __shfl_up_sync(0xffffffffu, v, 2);  if (lane >= 2)  v = fmaf(f2, u, v);
        u = __shfl_up_sync(0xffffffffu, v, 4);  if (lane >= 4)  v = fmaf(f3, u, v);
        u = __shfl_up_sync(0xffffffffu, v, 8);  if (lane >= 8)  v = fmaf(f4, u, v);
        u = __shfl_up_sync(0xffffffffu, v, 16); if (lane >= 16) v = fmaf(f5, u, v);

        // exclusive prefix, arithmetically: excl = (v - b) * c^-4
        // (lane 0: v == b exactly -> excl == 0; no SHFL, no predicate)
        float excl = (v - b) * inv_f1;

        // fold cross-chunk carry: true q entering this lane's segment
        float q = fmaf(clane, carry, excl);

        // carry for next chunk (broadcast lane 31's inclusive value)
        float v31 = __shfl_sync(0xffffffffu, v, 31);
        carry = fmaf(cchk, carry, v31);

        // ---- reconstruct q per element + fused PCEN epilogue ----
        float4 ov;
        q = fmaf(C_CONST, q, cur.x);  ov.x = pcen_epilogue(cur.x, q);
        q = fmaf(C_CONST, q, cur.y);  ov.y = pcen_epilogue(cur.y, q);
        q = fmaf(C_CONST, q, cur.z);  ov.z = pcen_epilogue(cur.z, q);
        q = fmaf(C_CONST, q, cur.w);  ov.w = pcen_epilogue(cur.w, q);

        reinterpret_cast<float4*>(orw + ch * CHUNK)[0] = ov;

        cur = nxt;
        nxt = nxt2;
    }
}

extern "C" void kernel_launch(void* const* d_in, const int* in_sizes, int n_in,
                              void* d_out, int out_size)
{
    const float* x = (const float*)d_in[0];
    float* out = (float*)d_out;

    int nrows  = in_sizes[0] / T_LEN;                              // 8192
    int blocks = (nrows + WARPS_PER_BLOCK - 1) / WARPS_PER_BLOCK;  // 1024

    pcen_kernel<<<blocks, BLOCK_THREADS>>>(x, out, nrows);
}